// round 6
// baseline (speedup 1.0000x reference)
#include <cuda_runtime.h>

#define BATCH 8
#define N_SEQ 1024
#define CDIM  256
#define RREL  16

// Scratch (device globals — no allocation allowed)
__device__ __align__(16) float g_Gt[CDIM * CDIM];        // Gt[m][k] = sum_c Wq[c][k]*Wk[c][m]
__device__ __align__(16) float g_wu[CDIM];               // Wq^T @ b_k
__device__ __align__(16) float g_wv[CDIM];               // Wk^T @ b_q
__device__ float g_cst;                                  // b_q . b_k
__device__ __align__(16) float g_A[BATCH * N_SEQ * CDIM];// Q @ G  (8 MB)
__device__ __align__(16) float g_u[BATCH * N_SEQ];
__device__ __align__(16) float g_v[BATCH * N_SEQ];
__device__ __align__(16) float g_Rt[RREL * N_SEQ * N_SEQ]; // R_map transposed to [r][i][j] (64 MB)

// ---------------------------------------------------------------------------
// prep: blocks 0..255 compute Gt; block 256 computes wu/wv/cst;
//       blocks 257.. transpose R_map[i][j][r] -> g_Rt[r][i][j].
// ---------------------------------------------------------------------------
__global__ void prep_w(const float* __restrict__ Wq, const float* __restrict__ Wk,
                       const float* __restrict__ bq, const float* __restrict__ bk,
                       const float* __restrict__ Rmap) {
    int tid = threadIdx.x;

    if (blockIdx.x >= 257) {
        // ---- R_map transpose: one block = (i, 256-wide j chunk) ----
        int tb = blockIdx.x - 257;          // 0..4095
        int i  = tb >> 2;                   // 0..1023
        int j0 = (tb & 3) << 8;             // 0,256,512,768
        __shared__ float s[256 * 17];       // [j][r] padded (17) for bank-free reads
        const float4* src = (const float4*)(Rmap + ((size_t)i * N_SEQ + j0) * RREL);
#pragma unroll
        for (int q = 0; q < 4; q++) {
            int idx = q * 256 + tid;        // 0..1023 float4s
            float4 f = src[idx];
            int j = idx >> 2;
            int rq = (idx & 3) << 2;
            s[j * 17 + rq + 0] = f.x; s[j * 17 + rq + 1] = f.y;
            s[j * 17 + rq + 2] = f.z; s[j * 17 + rq + 3] = f.w;
        }
        __syncthreads();
#pragma unroll
        for (int w = 0; w < 16; w++) {
            int idx = w * 256 + tid;        // 0..4095
            int r = idx >> 8;
            int j = idx & 255;
            g_Rt[((size_t)r * N_SEQ + i) * N_SEQ + j0 + j] = s[j * 17 + r];
        }
        return;
    }

    if (blockIdx.x == 256) {
        float su = 0.f, sv = 0.f;
        for (int c = 0; c < CDIM; c++) {
            su += Wq[c * CDIM + tid] * bk[c];
            sv += Wk[c * CDIM + tid] * bq[c];
        }
        g_wu[tid] = su;
        g_wv[tid] = sv;
        __shared__ float red[256];
        red[tid] = bq[tid] * bk[tid];
        __syncthreads();
        for (int s = 128; s > 0; s >>= 1) {
            if (tid < s) red[tid] += red[tid + s];
            __syncthreads();
        }
        if (tid == 0) g_cst = red[0];
        return;
    }

    // ---- Gt tile ----
    int bx = blockIdx.x;
    int mt = bx >> 4;
    int kt = bx & 15;
    int tm = tid >> 4;
    int tk = tid & 15;
    int lc = tid >> 4;
    int li = tid & 15;

    __shared__ float sq[16][16];
    __shared__ float sk[16][16];

    float acc = 0.f;
    for (int c0 = 0; c0 < CDIM; c0 += 16) {
        sq[lc][li] = Wq[(c0 + lc) * CDIM + kt * 16 + li];
        sk[lc][li] = Wk[(c0 + lc) * CDIM + mt * 16 + li];
        __syncthreads();
#pragma unroll
        for (int cc = 0; cc < 16; cc++)
            acc += sq[cc][tk] * sk[cc][tm];
        __syncthreads();
    }
    g_Gt[(mt * 16 + tm) * CDIM + kt * 16 + tk] = acc;
}

// ---------------------------------------------------------------------------
// compute_uv: u[row] = Q[row].wu ; v[row] = K[row].wv  (rows = B*N = 8192)
// ---------------------------------------------------------------------------
__global__ void compute_uv(const float* __restrict__ Q, const float* __restrict__ K) {
    int warp = threadIdx.x >> 5;
    int lane = threadIdx.x & 31;
    int row = blockIdx.x * 8 + warp;
    const float* qr = Q + (size_t)row * CDIM;
    const float* kr = K + (size_t)row * CDIM;
    float au = 0.f, av = 0.f;
#pragma unroll
    for (int t = 0; t < 8; t++) {
        int c = lane + t * 32;
        au += qr[c] * g_wu[c];
        av += kr[c] * g_wv[c];
    }
#pragma unroll
    for (int o = 16; o > 0; o >>= 1) {
        au += __shfl_down_sync(0xffffffffu, au, o);
        av += __shfl_down_sync(0xffffffffu, av, o);
    }
    if (lane == 0) {
        g_u[row] = au;
        g_v[row] = av;
    }
}

// ---------------------------------------------------------------------------
// gemm_A: A[row, m] = sum_k Q[row,k] * Gt[m,k]   (8192 x 256 x 256, NT)
// ---------------------------------------------------------------------------
__global__ __launch_bounds__(256, 2) void gemm_A(const float* __restrict__ Q) {
    int mt = blockIdx.x;
    int rt = blockIdx.y;
    int tid = threadIdx.x;
    int tx = tid & 15;
    int ty = tid >> 4;
    int lrow = tid >> 2;
    int lk = (tid & 3) << 2;

    __shared__ __align__(16) float As[2][16][128];
    __shared__ __align__(16) float Bs[2][16][64];

    const float* Ap = Q + (size_t)rt * 128 * CDIM;
    const float* Bp = g_Gt + (size_t)mt * 64 * CDIM;

    float4 ra0, ra1, rb0;

    auto ldg_stage = [&](int k0) {
        ra0 = *(const float4*)(Ap + (size_t)lrow * CDIM + k0 + lk);
        ra1 = *(const float4*)(Ap + (size_t)(64 + lrow) * CDIM + k0 + lk);
        rb0 = *(const float4*)(Bp + (size_t)lrow * CDIM + k0 + lk);
    };
    auto sts_stage = [&](int buf) {
        As[buf][lk + 0][lrow] = ra0.x; As[buf][lk + 1][lrow] = ra0.y;
        As[buf][lk + 2][lrow] = ra0.z; As[buf][lk + 3][lrow] = ra0.w;
        As[buf][lk + 0][64 + lrow] = ra1.x; As[buf][lk + 1][64 + lrow] = ra1.y;
        As[buf][lk + 2][64 + lrow] = ra1.z; As[buf][lk + 3][64 + lrow] = ra1.w;
        Bs[buf][lk + 0][lrow] = rb0.x; Bs[buf][lk + 1][lrow] = rb0.y;
        Bs[buf][lk + 2][lrow] = rb0.z; Bs[buf][lk + 3][lrow] = rb0.w;
    };

    float acc[8][4] = {};

    ldg_stage(0);
    sts_stage(0);
    __syncthreads();

    for (int s = 0; s < 16; s++) {
        int cur = s & 1;
        if (s < 15) ldg_stage((s + 1) * 16);
#pragma unroll
        for (int kk = 0; kk < 16; kk++) {
            float4 a0 = *(const float4*)&As[cur][kk][ty * 8];
            float4 a1 = *(const float4*)&As[cur][kk][ty * 8 + 4];
            float4 b0 = *(const float4*)&Bs[cur][kk][tx * 4];
            float av[8] = {a0.x, a0.y, a0.z, a0.w, a1.x, a1.y, a1.z, a1.w};
            float bv[4] = {b0.x, b0.y, b0.z, b0.w};
#pragma unroll
            for (int ii = 0; ii < 8; ii++)
#pragma unroll
                for (int jj = 0; jj < 4; jj++)
                    acc[ii][jj] += av[ii] * bv[jj];
        }
        if (s < 15) {
            sts_stage(cur ^ 1);
            __syncthreads();
        }
    }

    int row = rt * 128 + ty * 8;
    int m = mt * 64 + tx * 4;
#pragma unroll
    for (int ii = 0; ii < 8; ii++) {
        float4 o = {acc[ii][0], acc[ii][1], acc[ii][2], acc[ii][3]};
        *(float4*)&g_A[(size_t)(row + ii) * CDIM + m] = o;
    }
}

// ---------------------------------------------------------------------------
// main_fused v6: 128(i) x 64(j) tile, 8x8 micro, 128 threads, occ-3.
// Coalesced GEMM loaders (8 wavefronts/LDG vs 32 in v5) + transposed R_map
// so epilogue loads are j-contiguous like the stores.
//   scores = (A[b,i,:] . Key[b,j,:] + u[i] + v[j] + cst) / 16
//   out[b,r,i,j] = scores * Rt[r,i,j]
// grid (8 batch <- fastest for Rt L2 reuse, 128 tiles), 128 threads
// ---------------------------------------------------------------------------
__global__ __launch_bounds__(128, 3) void main_fused(const float* __restrict__ Key,
                                                     const float* __restrict__ Rmap_unused,
                                                     float* __restrict__ out) {
    int b = blockIdx.x;
    int tile = blockIdx.y;        // 0..127
    int it = tile >> 4;           // 0..7   (128 i-rows each)
    int jt = tile & 15;           // 0..15  (64 j-cols each)
    int tid = threadIdx.x;        // 0..127
    int tx = tid & 7;             // j dir (8 each)
    int ty = tid >> 3;            // i dir (8 each, 16 slots)

    __shared__ __align__(16) float As[2][16][128];  // [buf][k][i]
    __shared__ __align__(16) float Bs[2][16][64];   // [buf][k][j]

    const float* Ap = g_A + ((size_t)b * N_SEQ + it * 128) * CDIM;
    const float* Bp = Key + ((size_t)b * N_SEQ + jt * 64) * CDIM;

    float4 ra[4], rb[2];

    // coalesced loaders: 4 consecutive lanes cover one row's 64 B
    auto ldg_stage = [&](int k0) {
#pragma unroll
        for (int q = 0; q < 4; q++) {
            int idx = q * 128 + tid;            // 0..511 -> A row idx>>2, kq idx&3
            ra[q] = *(const float4*)(Ap + (size_t)(idx >> 2) * CDIM + k0 + ((idx & 3) << 2));
        }
#pragma unroll
        for (int q = 0; q < 2; q++) {
            int idx = q * 128 + tid;            // 0..255 -> B row idx>>2
            rb[q] = *(const float4*)(Bp + (size_t)(idx >> 2) * CDIM + k0 + ((idx & 3) << 2));
        }
    };
    auto sts_stage = [&](int buf) {
#pragma unroll
        for (int q = 0; q < 4; q++) {
            int idx = q * 128 + tid;
            int row = idx >> 2;
            int kq = (idx & 3) << 2;
            As[buf][kq + 0][row] = ra[q].x; As[buf][kq + 1][row] = ra[q].y;
            As[buf][kq + 2][row] = ra[q].z; As[buf][kq + 3][row] = ra[q].w;
        }
#pragma unroll
        for (int q = 0; q < 2; q++) {
            int idx = q * 128 + tid;
            int row = idx >> 2;
            int kq = (idx & 3) << 2;
            Bs[buf][kq + 0][row] = rb[q].x; Bs[buf][kq + 1][row] = rb[q].y;
            Bs[buf][kq + 2][row] = rb[q].z; Bs[buf][kq + 3][row] = rb[q].w;
        }
    };

    float acc[8][8] = {};

    ldg_stage(0);
    sts_stage(0);
    __syncthreads();

    for (int s = 0; s < 16; s++) {
        int cur = s & 1;
        if (s < 15) ldg_stage((s + 1) * 16);
#pragma unroll
        for (int kk = 0; kk < 16; kk++) {
            float4 a0 = *(const float4*)&As[cur][kk][ty * 8];
            float4 a1 = *(const float4*)&As[cur][kk][ty * 8 + 4];
            float4 b0 = *(const float4*)&Bs[cur][kk][tx * 8];
            float4 b1 = *(const float4*)&Bs[cur][kk][tx * 8 + 4];
            float av[8] = {a0.x, a0.y, a0.z, a0.w, a1.x, a1.y, a1.z, a1.w};
            float bv[8] = {b0.x, b0.y, b0.z, b0.w, b1.x, b1.y, b1.z, b1.w};
#pragma unroll
            for (int ii = 0; ii < 8; ii++)
#pragma unroll
                for (int jj = 0; jj < 8; jj++)
                    acc[ii][jj] += av[ii] * bv[jj];
        }
        if (s < 15) {
            sts_stage(cur ^ 1);    // ping-pong: single barrier per stage
            __syncthreads();
        }
    }

    // ---- epilogue: finalize scores ----
    int i0 = it * 128 + ty * 8;
    int j0 = jt * 64 + tx * 8;
    float cst = g_cst;
    float4 u0 = *(const float4*)&g_u[b * N_SEQ + i0];
    float4 u1 = *(const float4*)&g_u[b * N_SEQ + i0 + 4];
    float4 v0 = *(const float4*)&g_v[b * N_SEQ + j0];
    float4 v1 = *(const float4*)&g_v[b * N_SEQ + j0 + 4];
    float uu[8] = {u0.x, u0.y, u0.z, u0.w, u1.x, u1.y, u1.z, u1.w};
    float vv[8] = {v0.x, v0.y, v0.z, v0.w, v1.x, v1.y, v1.z, v1.w};

#pragma unroll
    for (int ii = 0; ii < 8; ii++)
#pragma unroll
        for (int jj = 0; jj < 8; jj++)
            acc[ii][jj] = (acc[ii][jj] + uu[ii] + vv[jj] + cst) * 0.0625f;

    // ---- relation-mask multiply + streaming store (Rt: j-contiguous) ----
    const size_t NN = (size_t)N_SEQ * N_SEQ;
#pragma unroll
    for (int ii = 0; ii < 8; ii++) {
        int i = i0 + ii;
        const float* rtp = g_Rt + (size_t)i * N_SEQ + j0;
        float* op = out + (size_t)(b * RREL) * NN + (size_t)i * N_SEQ + j0;
#pragma unroll
        for (int r = 0; r < RREL; r++) {
            float4 m0 = *(const float4*)(rtp + (size_t)r * NN);
            float4 m1 = *(const float4*)(rtp + (size_t)r * NN + 4);
            float4 o0, o1;
            o0.x = acc[ii][0] * m0.x; o0.y = acc[ii][1] * m0.y;
            o0.z = acc[ii][2] * m0.z; o0.w = acc[ii][3] * m0.w;
            o1.x = acc[ii][4] * m1.x; o1.y = acc[ii][5] * m1.y;
            o1.z = acc[ii][6] * m1.z; o1.w = acc[ii][7] * m1.w;
            float* dst = op + (size_t)r * NN;
            __stcs((float4*)dst, o0);
            __stcs((float4*)(dst + 4), o1);
        }
    }
}

// ---------------------------------------------------------------------------
extern "C" void kernel_launch(void* const* d_in, const int* in_sizes, int n_in,
                              void* d_out, int out_size) {
    const float* Q    = (const float*)d_in[0];
    const float* K    = (const float*)d_in[1];
    const float* Wq   = (const float*)d_in[2];
    const float* bq   = (const float*)d_in[3];
    const float* Wk   = (const float*)d_in[4];
    const float* bk   = (const float*)d_in[5];
    const float* Rmap = (const float*)d_in[6];
    float* out = (float*)d_out;

    prep_w<<<257 + 4096, 256>>>(Wq, Wk, bq, bk, Rmap);
    compute_uv<<<1024, 256>>>(Q, K);
    gemm_A<<<dim3(4, 64), 256>>>(Q);
    main_fused<<<dim3(8, 128), 128>>>(K, Rmap, out);
}

// round 7
// speedup vs baseline: 1.7503x; 1.7503x over previous
#include <cuda_runtime.h>

#define BATCH 8
#define N_SEQ 1024
#define CDIM  256
#define RREL  16

// Scratch (device globals — no allocation allowed)
__device__ __align__(16) float g_Gt[CDIM * CDIM];        // Gt[m][k] = sum_c Wq[c][k]*Wk[c][m]
__device__ __align__(16) float g_wu[CDIM];               // Wq^T @ b_k
__device__ __align__(16) float g_wv[CDIM];               // Wk^T @ b_q
__device__ float g_cst;                                  // b_q . b_k
__device__ __align__(16) float g_A[BATCH * N_SEQ * CDIM];// Q @ G  (8 MB)
__device__ __align__(16) float g_u[BATCH * N_SEQ];
__device__ __align__(16) float g_v[BATCH * N_SEQ];
__device__ __align__(16) float g_Rt[RREL * N_SEQ * N_SEQ]; // R_map transposed to [r][i][j] (64 MB)

// ---------------------------------------------------------------------------
// prep: blocks 0..255 compute Gt; block 256 computes wu/wv/cst;
//       blocks 257.. transpose R_map[i][j][r] -> g_Rt[r][i][j].
// ---------------------------------------------------------------------------
__global__ void prep_w(const float* __restrict__ Wq, const float* __restrict__ Wk,
                       const float* __restrict__ bq, const float* __restrict__ bk,
                       const float* __restrict__ Rmap) {
    int tid = threadIdx.x;

    if (blockIdx.x >= 257) {
        // ---- R_map transpose: one block = (i, 256-wide j chunk) ----
        int tb = blockIdx.x - 257;          // 0..4095
        int i  = tb >> 2;                   // 0..1023
        int j0 = (tb & 3) << 8;             // 0,256,512,768
        __shared__ float s[256 * 17];       // [j][r] padded (17) for bank-free reads
        const float4* src = (const float4*)(Rmap + ((size_t)i * N_SEQ + j0) * RREL);
#pragma unroll
        for (int q = 0; q < 4; q++) {
            int idx = q * 256 + tid;        // 0..1023 float4s
            float4 f = src[idx];
            int j = idx >> 2;
            int rq = (idx & 3) << 2;
            s[j * 17 + rq + 0] = f.x; s[j * 17 + rq + 1] = f.y;
            s[j * 17 + rq + 2] = f.z; s[j * 17 + rq + 3] = f.w;
        }
        __syncthreads();
#pragma unroll
        for (int w = 0; w < 16; w++) {
            int idx = w * 256 + tid;        // 0..4095
            int r = idx >> 8;
            int j = idx & 255;
            g_Rt[((size_t)r * N_SEQ + i) * N_SEQ + j0 + j] = s[j * 17 + r];
        }
        return;
    }

    if (blockIdx.x == 256) {
        float su = 0.f, sv = 0.f;
        for (int c = 0; c < CDIM; c++) {
            su += Wq[c * CDIM + tid] * bk[c];
            sv += Wk[c * CDIM + tid] * bq[c];
        }
        g_wu[tid] = su;
        g_wv[tid] = sv;
        __shared__ float red[256];
        red[tid] = bq[tid] * bk[tid];
        __syncthreads();
        for (int s = 128; s > 0; s >>= 1) {
            if (tid < s) red[tid] += red[tid + s];
            __syncthreads();
        }
        if (tid == 0) g_cst = red[0];
        return;
    }

    // ---- Gt tile ----
    int bx = blockIdx.x;
    int mt = bx >> 4;
    int kt = bx & 15;
    int tm = tid >> 4;
    int tk = tid & 15;
    int lc = tid >> 4;
    int li = tid & 15;

    __shared__ float sq[16][16];
    __shared__ float sk[16][16];

    float acc = 0.f;
    for (int c0 = 0; c0 < CDIM; c0 += 16) {
        sq[lc][li] = Wq[(c0 + lc) * CDIM + kt * 16 + li];
        sk[lc][li] = Wk[(c0 + lc) * CDIM + mt * 16 + li];
        __syncthreads();
#pragma unroll
        for (int cc = 0; cc < 16; cc++)
            acc += sq[cc][tk] * sk[cc][tm];
        __syncthreads();
    }
    g_Gt[(mt * 16 + tm) * CDIM + kt * 16 + tk] = acc;
}

// ---------------------------------------------------------------------------
// compute_uv: u[row] = Q[row].wu ; v[row] = K[row].wv  (rows = B*N = 8192)
// ---------------------------------------------------------------------------
__global__ void compute_uv(const float* __restrict__ Q, const float* __restrict__ K) {
    int warp = threadIdx.x >> 5;
    int lane = threadIdx.x & 31;
    int row = blockIdx.x * 8 + warp;
    const float* qr = Q + (size_t)row * CDIM;
    const float* kr = K + (size_t)row * CDIM;
    float au = 0.f, av = 0.f;
#pragma unroll
    for (int t = 0; t < 8; t++) {
        int c = lane + t * 32;
        au += qr[c] * g_wu[c];
        av += kr[c] * g_wv[c];
    }
#pragma unroll
    for (int o = 16; o > 0; o >>= 1) {
        au += __shfl_down_sync(0xffffffffu, au, o);
        av += __shfl_down_sync(0xffffffffu, av, o);
    }
    if (lane == 0) {
        g_u[row] = au;
        g_v[row] = av;
    }
}

// ---------------------------------------------------------------------------
// gemm_A: A[row, m] = sum_k Q[row,k] * Gt[m,k]   (8192 x 256 x 256, NT)
// ---------------------------------------------------------------------------
__global__ __launch_bounds__(256, 2) void gemm_A(const float* __restrict__ Q) {
    int mt = blockIdx.x;
    int rt = blockIdx.y;
    int tid = threadIdx.x;
    int tx = tid & 15;
    int ty = tid >> 4;
    int lrow = tid >> 2;
    int lk = (tid & 3) << 2;

    __shared__ __align__(16) float As[2][16][128];
    __shared__ __align__(16) float Bs[2][16][64];

    const float* Ap = Q + (size_t)rt * 128 * CDIM;
    const float* Bp = g_Gt + (size_t)mt * 64 * CDIM;

    float4 ra0, ra1, rb0;

    auto ldg_stage = [&](int k0) {
        ra0 = *(const float4*)(Ap + (size_t)lrow * CDIM + k0 + lk);
        ra1 = *(const float4*)(Ap + (size_t)(64 + lrow) * CDIM + k0 + lk);
        rb0 = *(const float4*)(Bp + (size_t)lrow * CDIM + k0 + lk);
    };
    auto sts_stage = [&](int buf) {
        As[buf][lk + 0][lrow] = ra0.x; As[buf][lk + 1][lrow] = ra0.y;
        As[buf][lk + 2][lrow] = ra0.z; As[buf][lk + 3][lrow] = ra0.w;
        As[buf][lk + 0][64 + lrow] = ra1.x; As[buf][lk + 1][64 + lrow] = ra1.y;
        As[buf][lk + 2][64 + lrow] = ra1.z; As[buf][lk + 3][64 + lrow] = ra1.w;
        Bs[buf][lk + 0][lrow] = rb0.x; Bs[buf][lk + 1][lrow] = rb0.y;
        Bs[buf][lk + 2][lrow] = rb0.z; Bs[buf][lk + 3][lrow] = rb0.w;
    };

    float acc[8][4] = {};

    ldg_stage(0);
    sts_stage(0);
    __syncthreads();

    for (int s = 0; s < 16; s++) {
        int cur = s & 1;
        if (s < 15) ldg_stage((s + 1) * 16);
#pragma unroll
        for (int kk = 0; kk < 16; kk++) {
            float4 a0 = *(const float4*)&As[cur][kk][ty * 8];
            float4 a1 = *(const float4*)&As[cur][kk][ty * 8 + 4];
            float4 b0 = *(const float4*)&Bs[cur][kk][tx * 4];
            float av[8] = {a0.x, a0.y, a0.z, a0.w, a1.x, a1.y, a1.z, a1.w};
            float bv[4] = {b0.x, b0.y, b0.z, b0.w};
#pragma unroll
            for (int ii = 0; ii < 8; ii++)
#pragma unroll
                for (int jj = 0; jj < 4; jj++)
                    acc[ii][jj] += av[ii] * bv[jj];
        }
        if (s < 15) {
            sts_stage(cur ^ 1);
            __syncthreads();
        }
    }

    int row = rt * 128 + ty * 8;
    int m = mt * 64 + tx * 4;
#pragma unroll
    for (int ii = 0; ii < 8; ii++) {
        float4 o = {acc[ii][0], acc[ii][1], acc[ii][2], acc[ii][3]};
        *(float4*)&g_A[(size_t)(row + ii) * CDIM + m] = o;
    }
}

// ---------------------------------------------------------------------------
// main_fused v7: 64x64 tile, 4x4 micro, 256 threads, occ-4 (32 warps/SM).
// The R6 lesson: warps/SM is first-order. Rt epilogue keeps loads coalesced.
//   scores = (A[b,i,:] . Key[b,j,:] + u[i] + v[j] + cst) / 16
//   out[b,r,i,j] = scores * Rt[r,i,j]
// grid (8 batch <- fastest for Rt L2 reuse, 256 tiles), 256 threads
// ---------------------------------------------------------------------------
__global__ __launch_bounds__(256, 4) void main_fused(const float* __restrict__ Key,
                                                     float* __restrict__ out) {
    int b = blockIdx.x;
    int tile = blockIdx.y;        // 0..255
    int it = tile >> 4;           // 0..15
    int jt = tile & 15;           // 0..15
    int tid = threadIdx.x;
    int tx = tid & 15;            // j dir (4 each)
    int ty = tid >> 4;            // i dir (4 each)
    int lrow = tid >> 2;          // 0..63
    int lk = (tid & 3) << 2;      // 0,4,8,12

    __shared__ __align__(16) float As[2][16][64];  // [buf][k][i]
    __shared__ __align__(16) float Bs[2][16][64];  // [buf][k][j]

    const float* Ap = g_A + ((size_t)b * N_SEQ + it * 64) * CDIM;
    const float* Bp = Key + ((size_t)b * N_SEQ + jt * 64) * CDIM;

    float4 ra, rb;

    auto ldg_stage = [&](int k0) {
        ra = *(const float4*)(Ap + (size_t)lrow * CDIM + k0 + lk);
        rb = *(const float4*)(Bp + (size_t)lrow * CDIM + k0 + lk);
    };
    auto sts_stage = [&](int buf) {
        As[buf][lk + 0][lrow] = ra.x; As[buf][lk + 1][lrow] = ra.y;
        As[buf][lk + 2][lrow] = ra.z; As[buf][lk + 3][lrow] = ra.w;
        Bs[buf][lk + 0][lrow] = rb.x; Bs[buf][lk + 1][lrow] = rb.y;
        Bs[buf][lk + 2][lrow] = rb.z; Bs[buf][lk + 3][lrow] = rb.w;
    };

    float acc[4][4] = {};

    ldg_stage(0);
    sts_stage(0);
    __syncthreads();

    for (int s = 0; s < 16; s++) {
        int cur = s & 1;
        if (s < 15) ldg_stage((s + 1) * 16);
#pragma unroll
        for (int kk = 0; kk < 16; kk++) {
            float4 a0 = *(const float4*)&As[cur][kk][ty * 4];
            float4 b0 = *(const float4*)&Bs[cur][kk][tx * 4];
            float av[4] = {a0.x, a0.y, a0.z, a0.w};
            float bv[4] = {b0.x, b0.y, b0.z, b0.w};
#pragma unroll
            for (int ii = 0; ii < 4; ii++)
#pragma unroll
                for (int jj = 0; jj < 4; jj++)
                    acc[ii][jj] += av[ii] * bv[jj];
        }
        if (s < 15) {
            sts_stage(cur ^ 1);    // ping-pong: single barrier per stage
            __syncthreads();
        }
    }

    // ---- epilogue: finalize scores ----
    int i0 = it * 64 + ty * 4;
    int j0 = jt * 64 + tx * 4;
    float cst = g_cst;
    float4 u0 = *(const float4*)&g_u[b * N_SEQ + i0];
    float4 v0 = *(const float4*)&g_v[b * N_SEQ + j0];
    float uu[4] = {u0.x, u0.y, u0.z, u0.w};
    float vv[4] = {v0.x, v0.y, v0.z, v0.w};

#pragma unroll
    for (int ii = 0; ii < 4; ii++)
#pragma unroll
        for (int jj = 0; jj < 4; jj++)
            acc[ii][jj] = (acc[ii][jj] + uu[ii] + vv[jj] + cst) * 0.0625f;

    // ---- relation-mask multiply + streaming store (Rt: j-contiguous) ----
    const size_t NN = (size_t)N_SEQ * N_SEQ;
#pragma unroll
    for (int ii = 0; ii < 4; ii++) {
        int i = i0 + ii;
        const float* rtp = g_Rt + (size_t)i * N_SEQ + j0;
        float* op = out + (size_t)(b * RREL) * NN + (size_t)i * N_SEQ + j0;
#pragma unroll
        for (int r = 0; r < RREL; r++) {
            float4 m0 = __ldg((const float4*)(rtp + (size_t)r * NN));
            float4 o0;
            o0.x = acc[ii][0] * m0.x;
            o0.y = acc[ii][1] * m0.y;
            o0.z = acc[ii][2] * m0.z;
            o0.w = acc[ii][3] * m0.w;
            __stcs((float4*)(op + (size_t)r * NN), o0);
        }
    }
}

// ---------------------------------------------------------------------------
extern "C" void kernel_launch(void* const* d_in, const int* in_sizes, int n_in,
                              void* d_out, int out_size) {
    const float* Q    = (const float*)d_in[0];
    const float* K    = (const float*)d_in[1];
    const float* Wq   = (const float*)d_in[2];
    const float* bq   = (const float*)d_in[3];
    const float* Wk   = (const float*)d_in[4];
    const float* bk   = (const float*)d_in[5];
    const float* Rmap = (const float*)d_in[6];
    float* out = (float*)d_out;

    prep_w<<<257 + 4096, 256>>>(Wq, Wk, bq, bk, Rmap);
    compute_uv<<<1024, 256>>>(Q, K);
    gemm_A<<<dim3(4, 64), 256>>>(Q);
    main_fused<<<dim3(8, 256), 256>>>(K, out);
}

// round 8
// speedup vs baseline: 1.8213x; 1.0406x over previous
#include <cuda_runtime.h>

#define BATCH 8
#define N_SEQ 1024
#define CDIM  256
#define RREL  16

// Scratch (device globals — no allocation allowed)
__device__ __align__(16) float g_Gt[CDIM * CDIM];        // Gt[m][k] = sum_c Wq[c][k]*Wk[c][m]
__device__ __align__(16) float g_wu[CDIM];               // Wq^T @ b_k
__device__ __align__(16) float g_wv[CDIM];               // Wk^T @ b_q
__device__ float g_cst;                                  // b_q . b_k
__device__ __align__(16) float g_A[BATCH * N_SEQ * CDIM];// Q @ G  (8 MB)
__device__ __align__(16) float g_u[BATCH * N_SEQ];
__device__ __align__(16) float g_v[BATCH * N_SEQ];
__device__ __align__(16) float g_Rt[RREL * N_SEQ * N_SEQ]; // R_map transposed to [r][i][j] (64 MB)

// ---------------------------------------------------------------------------
// prep: blocks 0..255 compute Gt; block 256 computes wu/wv/cst;
//       blocks 257.. transpose R_map[i][j][r] -> g_Rt[r][i][j].
// ---------------------------------------------------------------------------
__global__ void prep_w(const float* __restrict__ Wq, const float* __restrict__ Wk,
                       const float* __restrict__ bq, const float* __restrict__ bk,
                       const float* __restrict__ Rmap) {
    int tid = threadIdx.x;

    if (blockIdx.x >= 257) {
        // ---- R_map transpose: one block = (i, 256-wide j chunk) ----
        int tb = blockIdx.x - 257;          // 0..4095
        int i  = tb >> 2;                   // 0..1023
        int j0 = (tb & 3) << 8;             // 0,256,512,768
        __shared__ float s[256 * 17];       // [j][r] padded (17) for bank-free reads
        const float4* src = (const float4*)(Rmap + ((size_t)i * N_SEQ + j0) * RREL);
#pragma unroll
        for (int q = 0; q < 4; q++) {
            int idx = q * 256 + tid;        // 0..1023 float4s
            float4 f = src[idx];
            int j = idx >> 2;
            int rq = (idx & 3) << 2;
            s[j * 17 + rq + 0] = f.x; s[j * 17 + rq + 1] = f.y;
            s[j * 17 + rq + 2] = f.z; s[j * 17 + rq + 3] = f.w;
        }
        __syncthreads();
#pragma unroll
        for (int w = 0; w < 16; w++) {
            int idx = w * 256 + tid;        // 0..4095
            int r = idx >> 8;
            int j = idx & 255;
            g_Rt[((size_t)r * N_SEQ + i) * N_SEQ + j0 + j] = s[j * 17 + r];
        }
        return;
    }

    if (blockIdx.x == 256) {
        float su = 0.f, sv = 0.f;
        for (int c = 0; c < CDIM; c++) {
            su += Wq[c * CDIM + tid] * bk[c];
            sv += Wk[c * CDIM + tid] * bq[c];
        }
        g_wu[tid] = su;
        g_wv[tid] = sv;
        __shared__ float red[256];
        red[tid] = bq[tid] * bk[tid];
        __syncthreads();
        for (int s = 128; s > 0; s >>= 1) {
            if (tid < s) red[tid] += red[tid + s];
            __syncthreads();
        }
        if (tid == 0) g_cst = red[0];
        return;
    }

    // ---- Gt tile ----
    int bx = blockIdx.x;
    int mt = bx >> 4;
    int kt = bx & 15;
    int tm = tid >> 4;
    int tk = tid & 15;
    int lc = tid >> 4;
    int li = tid & 15;

    __shared__ float sq[16][16];
    __shared__ float sk[16][16];

    float acc = 0.f;
    for (int c0 = 0; c0 < CDIM; c0 += 16) {
        sq[lc][li] = Wq[(c0 + lc) * CDIM + kt * 16 + li];
        sk[lc][li] = Wk[(c0 + lc) * CDIM + mt * 16 + li];
        __syncthreads();
#pragma unroll
        for (int cc = 0; cc < 16; cc++)
            acc += sq[cc][tk] * sk[cc][tm];
        __syncthreads();
    }
    g_Gt[(mt * 16 + tm) * CDIM + kt * 16 + tk] = acc;
}

// ---------------------------------------------------------------------------
// compute_uv: u[row] = Q[row].wu ; v[row] = K[row].wv  (rows = B*N = 8192)
// ---------------------------------------------------------------------------
__global__ void compute_uv(const float* __restrict__ Q, const float* __restrict__ K) {
    int warp = threadIdx.x >> 5;
    int lane = threadIdx.x & 31;
    int row = blockIdx.x * 8 + warp;
    const float* qr = Q + (size_t)row * CDIM;
    const float* kr = K + (size_t)row * CDIM;
    float au = 0.f, av = 0.f;
#pragma unroll
    for (int t = 0; t < 8; t++) {
        int c = lane + t * 32;
        au += qr[c] * g_wu[c];
        av += kr[c] * g_wv[c];
    }
#pragma unroll
    for (int o = 16; o > 0; o >>= 1) {
        au += __shfl_down_sync(0xffffffffu, au, o);
        av += __shfl_down_sync(0xffffffffu, av, o);
    }
    if (lane == 0) {
        g_u[row] = au;
        g_v[row] = av;
    }
}

// ---------------------------------------------------------------------------
// gemm_A: A[row, m] = sum_k Q[row,k] * Gt[m,k]   (8192 x 256 x 256, NT)
// ---------------------------------------------------------------------------
__global__ __launch_bounds__(256, 2) void gemm_A(const float* __restrict__ Q) {
    int mt = blockIdx.x;
    int rt = blockIdx.y;
    int tid = threadIdx.x;
    int tx = tid & 15;
    int ty = tid >> 4;
    int lrow = tid >> 2;
    int lk = (tid & 3) << 2;

    __shared__ __align__(16) float As[2][16][128];
    __shared__ __align__(16) float Bs[2][16][64];

    const float* Ap = Q + (size_t)rt * 128 * CDIM;
    const float* Bp = g_Gt + (size_t)mt * 64 * CDIM;

    float4 ra0, ra1, rb0;

    auto ldg_stage = [&](int k0) {
        ra0 = *(const float4*)(Ap + (size_t)lrow * CDIM + k0 + lk);
        ra1 = *(const float4*)(Ap + (size_t)(64 + lrow) * CDIM + k0 + lk);
        rb0 = *(const float4*)(Bp + (size_t)lrow * CDIM + k0 + lk);
    };
    auto sts_stage = [&](int buf) {
        As[buf][lk + 0][lrow] = ra0.x; As[buf][lk + 1][lrow] = ra0.y;
        As[buf][lk + 2][lrow] = ra0.z; As[buf][lk + 3][lrow] = ra0.w;
        As[buf][lk + 0][64 + lrow] = ra1.x; As[buf][lk + 1][64 + lrow] = ra1.y;
        As[buf][lk + 2][64 + lrow] = ra1.z; As[buf][lk + 3][64 + lrow] = ra1.w;
        Bs[buf][lk + 0][lrow] = rb0.x; Bs[buf][lk + 1][lrow] = rb0.y;
        Bs[buf][lk + 2][lrow] = rb0.z; Bs[buf][lk + 3][lrow] = rb0.w;
    };

    float acc[8][4] = {};

    ldg_stage(0);
    sts_stage(0);
    __syncthreads();

    for (int s = 0; s < 16; s++) {
        int cur = s & 1;
        if (s < 15) ldg_stage((s + 1) * 16);
#pragma unroll
        for (int kk = 0; kk < 16; kk++) {
            float4 a0 = *(const float4*)&As[cur][kk][ty * 8];
            float4 a1 = *(const float4*)&As[cur][kk][ty * 8 + 4];
            float4 b0 = *(const float4*)&Bs[cur][kk][tx * 4];
            float av[8] = {a0.x, a0.y, a0.z, a0.w, a1.x, a1.y, a1.z, a1.w};
            float bv[4] = {b0.x, b0.y, b0.z, b0.w};
#pragma unroll
            for (int ii = 0; ii < 8; ii++)
#pragma unroll
                for (int jj = 0; jj < 4; jj++)
                    acc[ii][jj] += av[ii] * bv[jj];
        }
        if (s < 15) {
            sts_stage(cur ^ 1);
            __syncthreads();
        }
    }

    int row = rt * 128 + ty * 8;
    int m = mt * 64 + tx * 4;
#pragma unroll
    for (int ii = 0; ii < 8; ii++) {
        float4 o = {acc[ii][0], acc[ii][1], acc[ii][2], acc[ii][3]};
        *(float4*)&g_A[(size_t)(row + ii) * CDIM + m] = o;
    }
}

// ---------------------------------------------------------------------------
// main_fused v8: 128(i) x 64(j) tile, 8x4 micro, 256 threads, occ-3 (24 warps).
// vs v7 (4x4): per kk per warp 4 smem wavefronts feed 32 FMA/thread instead of
// 3 wf for 16 FMA -> 1.5x FMA per L1 wavefront; STS bytes per FMA halve.
// Epilogue keeps line-optimal j-contiguous mapping (tx = lane&15).
//   scores = (A[b,i,:] . Key[b,j,:] + u[i] + v[j] + cst) / 16
//   out[b,r,i,j] = scores * Rt[r,i,j]
// grid (8 batch <- fastest for Rt L2 reuse, 128 tiles), 256 threads
// ---------------------------------------------------------------------------
__global__ __launch_bounds__(256, 3) void main_fused(const float* __restrict__ Key,
                                                     float* __restrict__ out) {
    int b = blockIdx.x;
    int tile = blockIdx.y;        // 0..127
    int it = tile >> 4;           // 0..7   (128 i-rows each)
    int jt = tile & 15;           // 0..15  (64 j-cols each)
    int tid = threadIdx.x;
    int tx = tid & 15;            // j dir (4 each)
    int ty = tid >> 4;            // i dir (8 each)
    int lrow = tid >> 2;          // 0..63
    int lk = (tid & 3) << 2;      // 0,4,8,12

    __shared__ __align__(16) float As[2][16][128];  // [buf][k][i]
    __shared__ __align__(16) float Bs[2][16][64];   // [buf][k][j]

    const float* Ap = g_A + ((size_t)b * N_SEQ + it * 128) * CDIM;
    const float* Bp = Key + ((size_t)b * N_SEQ + jt * 64) * CDIM;

    float4 ra0, ra1, rb0;

    auto ldg_stage = [&](int k0) {
        ra0 = *(const float4*)(Ap + (size_t)lrow * CDIM + k0 + lk);
        ra1 = *(const float4*)(Ap + (size_t)(64 + lrow) * CDIM + k0 + lk);
        rb0 = *(const float4*)(Bp + (size_t)lrow * CDIM + k0 + lk);
    };
    auto sts_stage = [&](int buf) {
        As[buf][lk + 0][lrow] = ra0.x; As[buf][lk + 1][lrow] = ra0.y;
        As[buf][lk + 2][lrow] = ra0.z; As[buf][lk + 3][lrow] = ra0.w;
        As[buf][lk + 0][64 + lrow] = ra1.x; As[buf][lk + 1][64 + lrow] = ra1.y;
        As[buf][lk + 2][64 + lrow] = ra1.z; As[buf][lk + 3][64 + lrow] = ra1.w;
        Bs[buf][lk + 0][lrow] = rb0.x; Bs[buf][lk + 1][lrow] = rb0.y;
        Bs[buf][lk + 2][lrow] = rb0.z; Bs[buf][lk + 3][lrow] = rb0.w;
    };

    float acc[8][4] = {};

    ldg_stage(0);
    sts_stage(0);
    __syncthreads();

    for (int s = 0; s < 16; s++) {
        int cur = s & 1;
        if (s < 15) ldg_stage((s + 1) * 16);
#pragma unroll
        for (int kk = 0; kk < 16; kk++) {
            float4 a0 = *(const float4*)&As[cur][kk][ty * 8];
            float4 a1 = *(const float4*)&As[cur][kk][ty * 8 + 4];
            float4 b0 = *(const float4*)&Bs[cur][kk][tx * 4];
            float av[8] = {a0.x, a0.y, a0.z, a0.w, a1.x, a1.y, a1.z, a1.w};
            float bv[4] = {b0.x, b0.y, b0.z, b0.w};
#pragma unroll
            for (int ii = 0; ii < 8; ii++)
#pragma unroll
                for (int jj = 0; jj < 4; jj++)
                    acc[ii][jj] += av[ii] * bv[jj];
        }
        if (s < 15) {
            sts_stage(cur ^ 1);    // ping-pong: single barrier per stage
            __syncthreads();
        }
    }

    // ---- epilogue: finalize scores ----
    int i0 = it * 128 + ty * 8;
    int j0 = jt * 64 + tx * 4;
    float cst = g_cst;
    float4 u0 = *(const float4*)&g_u[b * N_SEQ + i0];
    float4 u1 = *(const float4*)&g_u[b * N_SEQ + i0 + 4];
    float4 v0 = *(const float4*)&g_v[b * N_SEQ + j0];
    float uu[8] = {u0.x, u0.y, u0.z, u0.w, u1.x, u1.y, u1.z, u1.w};
    float vv[4] = {v0.x, v0.y, v0.z, v0.w};

#pragma unroll
    for (int ii = 0; ii < 8; ii++)
#pragma unroll
        for (int jj = 0; jj < 4; jj++)
            acc[ii][jj] = (acc[ii][jj] + uu[ii] + vv[jj] + cst) * 0.0625f;

    // ---- relation-mask multiply + streaming store (Rt: j-contiguous) ----
    const size_t NN = (size_t)N_SEQ * N_SEQ;
#pragma unroll
    for (int ii = 0; ii < 8; ii++) {
        int i = i0 + ii;
        const float* rtp = g_Rt + (size_t)i * N_SEQ + j0;
        float* op = out + (size_t)(b * RREL) * NN + (size_t)i * N_SEQ + j0;
#pragma unroll
        for (int r = 0; r < RREL; r++) {
            float4 m0 = __ldg((const float4*)(rtp + (size_t)r * NN));
            float4 o0;
            o0.x = acc[ii][0] * m0.x;
            o0.y = acc[ii][1] * m0.y;
            o0.z = acc[ii][2] * m0.z;
            o0.w = acc[ii][3] * m0.w;
            __stcs((float4*)(op + (size_t)r * NN), o0);
        }
    }
}

// ---------------------------------------------------------------------------
extern "C" void kernel_launch(void* const* d_in, const int* in_sizes, int n_in,
                              void* d_out, int out_size) {
    const float* Q    = (const float*)d_in[0];
    const float* K    = (const float*)d_in[1];
    const float* Wq   = (const float*)d_in[2];
    const float* bq   = (const float*)d_in[3];
    const float* Wk   = (const float*)d_in[4];
    const float* bk   = (const float*)d_in[5];
    const float* Rmap = (const float*)d_in[6];
    float* out = (float*)d_out;

    prep_w<<<257 + 4096, 256>>>(Wq, Wk, bq, bk, Rmap);
    compute_uv<<<1024, 256>>>(Q, K);
    gemm_A<<<dim3(4, 64), 256>>>(Q);
    main_fused<<<dim3(8, 128), 256>>>(K, out);
}

// round 9
// speedup vs baseline: 1.8521x; 1.0169x over previous
#include <cuda_runtime.h>

#define BATCH 8
#define N_SEQ 1024
#define CDIM  256
#define RREL  16

// Padded smem strides: lk*STRIDE mod 32 banks = {0,16,0,16} -> 2-way STS
// conflicts instead of 4-way at stride 128/64. Must stay ==0 mod 4 floats
// for LDS.128 alignment.
#define SA 132
#define SB 68

// Scratch (device globals — no allocation allowed)
__device__ __align__(16) float g_Gt[CDIM * CDIM];        // Gt[m][k] = sum_c Wq[c][k]*Wk[c][m]
__device__ __align__(16) float g_wu[CDIM];               // Wq^T @ b_k
__device__ __align__(16) float g_wv[CDIM];               // Wk^T @ b_q
__device__ float g_cst;                                  // b_q . b_k
__device__ __align__(16) float g_A[BATCH * N_SEQ * CDIM];// Q @ G  (8 MB)
__device__ __align__(16) float g_u[BATCH * N_SEQ];
__device__ __align__(16) float g_v[BATCH * N_SEQ];
__device__ __align__(16) float g_Rt[RREL * N_SEQ * N_SEQ]; // R_map transposed to [r][i][j] (64 MB)

// ---------------------------------------------------------------------------
// prep: blocks 0..255 compute Gt; block 256 computes wu/wv/cst;
//       blocks 257.. transpose R_map[i][j][r] -> g_Rt[r][i][j].
// ---------------------------------------------------------------------------
__global__ void prep_w(const float* __restrict__ Wq, const float* __restrict__ Wk,
                       const float* __restrict__ bq, const float* __restrict__ bk,
                       const float* __restrict__ Rmap) {
    int tid = threadIdx.x;

    if (blockIdx.x >= 257) {
        // ---- R_map transpose: one block = (i, 256-wide j chunk) ----
        int tb = blockIdx.x - 257;          // 0..4095
        int i  = tb >> 2;                   // 0..1023
        int j0 = (tb & 3) << 8;             // 0,256,512,768
        __shared__ float s[256 * 17];       // [j][r] padded (17) for bank-free reads
        const float4* src = (const float4*)(Rmap + ((size_t)i * N_SEQ + j0) * RREL);
#pragma unroll
        for (int q = 0; q < 4; q++) {
            int idx = q * 256 + tid;        // 0..1023 float4s
            float4 f = src[idx];
            int j = idx >> 2;
            int rq = (idx & 3) << 2;
            s[j * 17 + rq + 0] = f.x; s[j * 17 + rq + 1] = f.y;
            s[j * 17 + rq + 2] = f.z; s[j * 17 + rq + 3] = f.w;
        }
        __syncthreads();
        // float4 stores: lane t covers j-quad (tid&63), r = tid>>6 (+4 per w)
        int jq = (tid & 63) << 2;
        int r0 = tid >> 6;                  // 0..3
#pragma unroll
        for (int w = 0; w < 4; w++) {
            int r = r0 * 4 + w;
            float4 o;
            o.x = s[(jq + 0) * 17 + r];
            o.y = s[(jq + 1) * 17 + r];
            o.z = s[(jq + 2) * 17 + r];
            o.w = s[(jq + 3) * 17 + r];
            *(float4*)&g_Rt[((size_t)r * N_SEQ + i) * N_SEQ + j0 + jq] = o;
        }
        return;
    }

    if (blockIdx.x == 256) {
        float su = 0.f, sv = 0.f;
        for (int c = 0; c < CDIM; c++) {
            su += Wq[c * CDIM + tid] * bk[c];
            sv += Wk[c * CDIM + tid] * bq[c];
        }
        g_wu[tid] = su;
        g_wv[tid] = sv;
        __shared__ float red[256];
        red[tid] = bq[tid] * bk[tid];
        __syncthreads();
        for (int s = 128; s > 0; s >>= 1) {
            if (tid < s) red[tid] += red[tid + s];
            __syncthreads();
        }
        if (tid == 0) g_cst = red[0];
        return;
    }

    // ---- Gt tile ----
    int bx = blockIdx.x;
    int mt = bx >> 4;
    int kt = bx & 15;
    int tm = tid >> 4;
    int tk = tid & 15;
    int lc = tid >> 4;
    int li = tid & 15;

    __shared__ float sq[16][16];
    __shared__ float sk[16][16];

    float acc = 0.f;
    for (int c0 = 0; c0 < CDIM; c0 += 16) {
        sq[lc][li] = Wq[(c0 + lc) * CDIM + kt * 16 + li];
        sk[lc][li] = Wk[(c0 + lc) * CDIM + mt * 16 + li];
        __syncthreads();
#pragma unroll
        for (int cc = 0; cc < 16; cc++)
            acc += sq[cc][tk] * sk[cc][tm];
        __syncthreads();
    }
    g_Gt[(mt * 16 + tm) * CDIM + kt * 16 + tk] = acc;
}

// ---------------------------------------------------------------------------
// compute_uv: u[row] = Q[row].wu ; v[row] = K[row].wv  (rows = B*N = 8192)
// ---------------------------------------------------------------------------
__global__ void compute_uv(const float* __restrict__ Q, const float* __restrict__ K) {
    int warp = threadIdx.x >> 5;
    int lane = threadIdx.x & 31;
    int row = blockIdx.x * 8 + warp;
    const float* qr = Q + (size_t)row * CDIM;
    const float* kr = K + (size_t)row * CDIM;
    float au = 0.f, av = 0.f;
#pragma unroll
    for (int t = 0; t < 8; t++) {
        int c = lane + t * 32;
        au += qr[c] * g_wu[c];
        av += kr[c] * g_wv[c];
    }
#pragma unroll
    for (int o = 16; o > 0; o >>= 1) {
        au += __shfl_down_sync(0xffffffffu, au, o);
        av += __shfl_down_sync(0xffffffffu, av, o);
    }
    if (lane == 0) {
        g_u[row] = au;
        g_v[row] = av;
    }
}

// ---------------------------------------------------------------------------
// gemm_A: A[row, m] = sum_k Q[row,k] * Gt[m,k]   (8192 x 256 x 256, NT)
// padded smem strides -> 2-way STS conflicts (was 4-way)
// ---------------------------------------------------------------------------
__global__ __launch_bounds__(256, 2) void gemm_A(const float* __restrict__ Q) {
    int mt = blockIdx.x;
    int rt = blockIdx.y;
    int tid = threadIdx.x;
    int tx = tid & 15;
    int ty = tid >> 4;
    int lrow = tid >> 2;
    int lk = (tid & 3) << 2;

    __shared__ __align__(16) float As[2][16][SA];
    __shared__ __align__(16) float Bs[2][16][SB];

    const float* Ap = Q + (size_t)rt * 128 * CDIM;
    const float* Bp = g_Gt + (size_t)mt * 64 * CDIM;

    float4 ra0, ra1, rb0;

    auto ldg_stage = [&](int k0) {
        ra0 = *(const float4*)(Ap + (size_t)lrow * CDIM + k0 + lk);
        ra1 = *(const float4*)(Ap + (size_t)(64 + lrow) * CDIM + k0 + lk);
        rb0 = *(const float4*)(Bp + (size_t)lrow * CDIM + k0 + lk);
    };
    auto sts_stage = [&](int buf) {
        As[buf][lk + 0][lrow] = ra0.x; As[buf][lk + 1][lrow] = ra0.y;
        As[buf][lk + 2][lrow] = ra0.z; As[buf][lk + 3][lrow] = ra0.w;
        As[buf][lk + 0][64 + lrow] = ra1.x; As[buf][lk + 1][64 + lrow] = ra1.y;
        As[buf][lk + 2][64 + lrow] = ra1.z; As[buf][lk + 3][64 + lrow] = ra1.w;
        Bs[buf][lk + 0][lrow] = rb0.x; Bs[buf][lk + 1][lrow] = rb0.y;
        Bs[buf][lk + 2][lrow] = rb0.z; Bs[buf][lk + 3][lrow] = rb0.w;
    };

    float acc[8][4] = {};

    ldg_stage(0);
    sts_stage(0);
    __syncthreads();

    for (int s = 0; s < 16; s++) {
        int cur = s & 1;
        if (s < 15) ldg_stage((s + 1) * 16);
#pragma unroll
        for (int kk = 0; kk < 16; kk++) {
            float4 a0 = *(const float4*)&As[cur][kk][ty * 8];
            float4 a1 = *(const float4*)&As[cur][kk][ty * 8 + 4];
            float4 b0 = *(const float4*)&Bs[cur][kk][tx * 4];
            float av[8] = {a0.x, a0.y, a0.z, a0.w, a1.x, a1.y, a1.z, a1.w};
            float bv[4] = {b0.x, b0.y, b0.z, b0.w};
#pragma unroll
            for (int ii = 0; ii < 8; ii++)
#pragma unroll
                for (int jj = 0; jj < 4; jj++)
                    acc[ii][jj] += av[ii] * bv[jj];
        }
        if (s < 15) {
            sts_stage(cur ^ 1);
            __syncthreads();
        }
    }

    int row = rt * 128 + ty * 8;
    int m = mt * 64 + tx * 4;
#pragma unroll
    for (int ii = 0; ii < 8; ii++) {
        float4 o = {acc[ii][0], acc[ii][1], acc[ii][2], acc[ii][3]};
        *(float4*)&g_A[(size_t)(row + ii) * CDIM + m] = o;
    }
}

// ---------------------------------------------------------------------------
// main_fused v9: 128(i) x 64(j) tile, 8x4 micro, 256 threads, occ-3.
// Padded smem strides (SA=132, SB=68): STS bank conflicts 4-way -> 2-way.
//   scores = (A[b,i,:] . Key[b,j,:] + u[i] + v[j] + cst) / 16
//   out[b,r,i,j] = scores * Rt[r,i,j]
// grid (8 batch <- fastest for Rt L2 reuse, 128 tiles), 256 threads
// ---------------------------------------------------------------------------
__global__ __launch_bounds__(256, 3) void main_fused(const float* __restrict__ Key,
                                                     float* __restrict__ out) {
    int b = blockIdx.x;
    int tile = blockIdx.y;        // 0..127
    int it = tile >> 4;           // 0..7   (128 i-rows each)
    int jt = tile & 15;           // 0..15  (64 j-cols each)
    int tid = threadIdx.x;
    int tx = tid & 15;            // j dir (4 each)
    int ty = tid >> 4;            // i dir (8 each)
    int lrow = tid >> 2;          // 0..63
    int lk = (tid & 3) << 2;      // 0,4,8,12

    __shared__ __align__(16) float As[2][16][SA];  // [buf][k][i] padded
    __shared__ __align__(16) float Bs[2][16][SB];  // [buf][k][j] padded

    const float* Ap = g_A + ((size_t)b * N_SEQ + it * 128) * CDIM;
    const float* Bp = Key + ((size_t)b * N_SEQ + jt * 64) * CDIM;

    float4 ra0, ra1, rb0;

    auto ldg_stage = [&](int k0) {
        ra0 = *(const float4*)(Ap + (size_t)lrow * CDIM + k0 + lk);
        ra1 = *(const float4*)(Ap + (size_t)(64 + lrow) * CDIM + k0 + lk);
        rb0 = *(const float4*)(Bp + (size_t)lrow * CDIM + k0 + lk);
    };
    auto sts_stage = [&](int buf) {
        As[buf][lk + 0][lrow] = ra0.x; As[buf][lk + 1][lrow] = ra0.y;
        As[buf][lk + 2][lrow] = ra0.z; As[buf][lk + 3][lrow] = ra0.w;
        As[buf][lk + 0][64 + lrow] = ra1.x; As[buf][lk + 1][64 + lrow] = ra1.y;
        As[buf][lk + 2][64 + lrow] = ra1.z; As[buf][lk + 3][64 + lrow] = ra1.w;
        Bs[buf][lk + 0][lrow] = rb0.x; Bs[buf][lk + 1][lrow] = rb0.y;
        Bs[buf][lk + 2][lrow] = rb0.z; Bs[buf][lk + 3][lrow] = rb0.w;
    };

    float acc[8][4] = {};

    ldg_stage(0);
    sts_stage(0);
    __syncthreads();

    for (int s = 0; s < 16; s++) {
        int cur = s & 1;
        if (s < 15) ldg_stage((s + 1) * 16);
#pragma unroll
        for (int kk = 0; kk < 16; kk++) {
            float4 a0 = *(const float4*)&As[cur][kk][ty * 8];
            float4 a1 = *(const float4*)&As[cur][kk][ty * 8 + 4];
            float4 b0 = *(const float4*)&Bs[cur][kk][tx * 4];
            float av[8] = {a0.x, a0.y, a0.z, a0.w, a1.x, a1.y, a1.z, a1.w};
            float bv[4] = {b0.x, b0.y, b0.z, b0.w};
#pragma unroll
            for (int ii = 0; ii < 8; ii++)
#pragma unroll
                for (int jj = 0; jj < 4; jj++)
                    acc[ii][jj] += av[ii] * bv[jj];
        }
        if (s < 15) {
            sts_stage(cur ^ 1);    // ping-pong: single barrier per stage
            __syncthreads();
        }
    }

    // ---- epilogue: finalize scores ----
    int i0 = it * 128 + ty * 8;
    int j0 = jt * 64 + tx * 4;
    float cst = g_cst;
    float4 u0 = *(const float4*)&g_u[b * N_SEQ + i0];
    float4 u1 = *(const float4*)&g_u[b * N_SEQ + i0 + 4];
    float4 v0 = *(const float4*)&g_v[b * N_SEQ + j0];
    float uu[8] = {u0.x, u0.y, u0.z, u0.w, u1.x, u1.y, u1.z, u1.w};
    float vv[4] = {v0.x, v0.y, v0.z, v0.w};

#pragma unroll
    for (int ii = 0; ii < 8; ii++)
#pragma unroll
        for (int jj = 0; jj < 4; jj++)
            acc[ii][jj] = (acc[ii][jj] + uu[ii] + vv[jj] + cst) * 0.0625f;

    // ---- relation-mask multiply + streaming store (Rt: j-contiguous) ----
    const size_t NN = (size_t)N_SEQ * N_SEQ;
#pragma unroll
    for (int ii = 0; ii < 8; ii++) {
        int i = i0 + ii;
        const float* rtp = g_Rt + (size_t)i * N_SEQ + j0;
        float* op = out + (size_t)(b * RREL) * NN + (size_t)i * N_SEQ + j0;
#pragma unroll
        for (int r = 0; r < RREL; r++) {
            float4 m0 = __ldg((const float4*)(rtp + (size_t)r * NN));
            float4 o0;
            o0.x = acc[ii][0] * m0.x;
            o0.y = acc[ii][1] * m0.y;
            o0.z = acc[ii][2] * m0.z;
            o0.w = acc[ii][3] * m0.w;
            __stcs((float4*)(op + (size_t)r * NN), o0);
        }
    }
}

// ---------------------------------------------------------------------------
extern "C" void kernel_launch(void* const* d_in, const int* in_sizes, int n_in,
                              void* d_out, int out_size) {
    const float* Q    = (const float*)d_in[0];
    const float* K    = (const float*)d_in[1];
    const float* Wq   = (const float*)d_in[2];
    const float* bq   = (const float*)d_in[3];
    const float* Wk   = (const float*)d_in[4];
    const float* bk   = (const float*)d_in[5];
    const float* Rmap = (const float*)d_in[6];
    float* out = (float*)d_out;

    prep_w<<<257 + 4096, 256>>>(Wq, Wk, bq, bk, Rmap);
    compute_uv<<<1024, 256>>>(Q, K);
    gemm_A<<<dim3(4, 64), 256>>>(Q);
    main_fused<<<dim3(8, 128), 256>>>(K, out);
}

// round 10
// speedup vs baseline: 1.9946x; 1.0769x over previous
#include <cuda_runtime.h>

#define BATCH 8
#define N_SEQ 1024
#define CDIM  256
#define RREL  16

// Padded smem strides (R9: 2-way STS conflicts instead of 4-way)
#define SA 132
#define SB 68

// Scratch (device globals — no allocation allowed)
__device__ __align__(16) float g_Gt[CDIM * CDIM];        // Gt[m][k] = sum_c Wq[c][k]*Wk[c][m]
__device__ __align__(16) float g_wu[CDIM];               // Wq^T @ b_k
__device__ __align__(16) float g_wv[CDIM];               // Wk^T @ b_q
__device__ float g_cst;                                  // b_q . b_k
__device__ __align__(16) float g_A[BATCH * N_SEQ * CDIM];// Q @ G  (8 MB)
__device__ __align__(16) float g_u[BATCH * N_SEQ];
__device__ __align__(16) float g_v[BATCH * N_SEQ];
__device__ __align__(16) float g_Rt[RREL * N_SEQ * N_SEQ]; // R_map transposed [r][i][j] (64 MB)

// ---------------------------------------------------------------------------
// prep_w: blocks 0..255 compute Gt; block 256 computes wu/wv/cst.  (~8 us)
// ---------------------------------------------------------------------------
__global__ void prep_w(const float* __restrict__ Wq, const float* __restrict__ Wk,
                       const float* __restrict__ bq, const float* __restrict__ bk) {
    int tid = threadIdx.x;

    if (blockIdx.x == 256) {
        float su = 0.f, sv = 0.f;
        for (int c = 0; c < CDIM; c++) {
            su += Wq[c * CDIM + tid] * bk[c];
            sv += Wk[c * CDIM + tid] * bq[c];
        }
        g_wu[tid] = su;
        g_wv[tid] = sv;
        __shared__ float red[256];
        red[tid] = bq[tid] * bk[tid];
        __syncthreads();
        for (int s = 128; s > 0; s >>= 1) {
            if (tid < s) red[tid] += red[tid + s];
            __syncthreads();
        }
        if (tid == 0) g_cst = red[0];
        return;
    }

    int bx = blockIdx.x;
    int mt = bx >> 4;
    int kt = bx & 15;
    int tm = tid >> 4;
    int tk = tid & 15;
    int lc = tid >> 4;
    int li = tid & 15;

    __shared__ float sq[16][16];
    __shared__ float sk[16][16];

    float acc = 0.f;
    for (int c0 = 0; c0 < CDIM; c0 += 16) {
        sq[lc][li] = Wq[(c0 + lc) * CDIM + kt * 16 + li];
        sk[lc][li] = Wk[(c0 + lc) * CDIM + mt * 16 + li];
        __syncthreads();
#pragma unroll
        for (int cc = 0; cc < 16; cc++)
            acc += sq[cc][tk] * sk[cc][tm];
        __syncthreads();
    }
    g_Gt[(mt * 16 + tm) * CDIM + kt * 16 + tk] = acc;
}

// ---------------------------------------------------------------------------
// mega: heterogeneous launch that fills the machine.
//   blocks [0,256):         gemm_A  (A = Q @ G), 128x64 tile, 8x4 micro
//   blocks [256,4352):      Rt transpose (R_map[i][j][r] -> g_Rt[r][i][j])
//   blocks [4352,5376):     compute_uv
// The transpose + uv have no dependence on the GEMM; running them in the same
// launch overlaps their DRAM traffic with GEMM compute on otherwise-idle SMs.
// ---------------------------------------------------------------------------
__global__ __launch_bounds__(256, 2) void mega(const float* __restrict__ Q,
                                               const float* __restrict__ K,
                                               const float* __restrict__ Rmap) {
    __shared__ __align__(16) float smem[6400];   // union buffer (25.6 KB)
    int tid = threadIdx.x;
    int bx = blockIdx.x;

    if (bx < 256) {
        // ================= gemm_A branch =================
        int mt = bx & 3;
        int rt = bx >> 2;
        int tx = tid & 15;
        int ty = tid >> 4;
        int lrow = tid >> 2;
        int lk = (tid & 3) << 2;

        // As[2][16][SA] then Bs[2][16][SB]
        float (*As)[16][SA] = (float (*)[16][SA])smem;
        float (*Bs)[16][SB] = (float (*)[16][SB])(smem + 2 * 16 * SA);

        const float* Ap = Q + (size_t)rt * 128 * CDIM;
        const float* Bp = g_Gt + (size_t)mt * 64 * CDIM;

        float4 ra0, ra1, rb0;

        auto ldg_stage = [&](int k0) {
            ra0 = *(const float4*)(Ap + (size_t)lrow * CDIM + k0 + lk);
            ra1 = *(const float4*)(Ap + (size_t)(64 + lrow) * CDIM + k0 + lk);
            rb0 = *(const float4*)(Bp + (size_t)lrow * CDIM + k0 + lk);
        };
        auto sts_stage = [&](int buf) {
            As[buf][lk + 0][lrow] = ra0.x; As[buf][lk + 1][lrow] = ra0.y;
            As[buf][lk + 2][lrow] = ra0.z; As[buf][lk + 3][lrow] = ra0.w;
            As[buf][lk + 0][64 + lrow] = ra1.x; As[buf][lk + 1][64 + lrow] = ra1.y;
            As[buf][lk + 2][64 + lrow] = ra1.z; As[buf][lk + 3][64 + lrow] = ra1.w;
            Bs[buf][lk + 0][lrow] = rb0.x; Bs[buf][lk + 1][lrow] = rb0.y;
            Bs[buf][lk + 2][lrow] = rb0.z; Bs[buf][lk + 3][lrow] = rb0.w;
        };

        float acc[8][4] = {};

        ldg_stage(0);
        sts_stage(0);
        __syncthreads();

        for (int s = 0; s < 16; s++) {
            int cur = s & 1;
            if (s < 15) ldg_stage((s + 1) * 16);
#pragma unroll
            for (int kk = 0; kk < 16; kk++) {
                float4 a0 = *(const float4*)&As[cur][kk][ty * 8];
                float4 a1 = *(const float4*)&As[cur][kk][ty * 8 + 4];
                float4 b0 = *(const float4*)&Bs[cur][kk][tx * 4];
                float av[8] = {a0.x, a0.y, a0.z, a0.w, a1.x, a1.y, a1.z, a1.w};
                float bv[4] = {b0.x, b0.y, b0.z, b0.w};
#pragma unroll
                for (int ii = 0; ii < 8; ii++)
#pragma unroll
                    for (int jj = 0; jj < 4; jj++)
                        acc[ii][jj] += av[ii] * bv[jj];
            }
            if (s < 15) {
                sts_stage(cur ^ 1);
                __syncthreads();
            }
        }

        int row = rt * 128 + ty * 8;
        int m = mt * 64 + tx * 4;
#pragma unroll
        for (int ii = 0; ii < 8; ii++) {
            float4 o = {acc[ii][0], acc[ii][1], acc[ii][2], acc[ii][3]};
            *(float4*)&g_A[(size_t)(row + ii) * CDIM + m] = o;
        }
        return;
    }

    if (bx < 256 + 4096) {
        // ================= Rt transpose branch =================
        int tb = bx - 256;                  // 0..4095
        int i  = tb >> 2;                   // 0..1023
        int j0 = (tb & 3) << 8;             // 0,256,512,768
        float* s = smem;                    // uses 256*17 = 4352 floats
        const float4* src = (const float4*)(Rmap + ((size_t)i * N_SEQ + j0) * RREL);
#pragma unroll
        for (int q = 0; q < 4; q++) {
            int idx = q * 256 + tid;        // 0..1023 float4s
            float4 f = src[idx];
            int j = idx >> 2;
            int rq = (idx & 3) << 2;
            s[j * 17 + rq + 0] = f.x; s[j * 17 + rq + 1] = f.y;
            s[j * 17 + rq + 2] = f.z; s[j * 17 + rq + 3] = f.w;
        }
        __syncthreads();
        int jq = (tid & 63) << 2;
        int r0 = tid >> 6;                  // 0..3
#pragma unroll
        for (int w = 0; w < 4; w++) {
            int r = r0 * 4 + w;
            float4 o;
            o.x = s[(jq + 0) * 17 + r];
            o.y = s[(jq + 1) * 17 + r];
            o.z = s[(jq + 2) * 17 + r];
            o.w = s[(jq + 3) * 17 + r];
            *(float4*)&g_Rt[((size_t)r * N_SEQ + i) * N_SEQ + j0 + jq] = o;
        }
        return;
    }

    // ================= compute_uv branch =================
    {
        int ub = bx - (256 + 4096);         // 0..1023
        int warp = tid >> 5;
        int lane = tid & 31;
        int row = ub * 8 + warp;
        const float* qr = Q + (size_t)row * CDIM;
        const float* kr = K + (size_t)row * CDIM;
        float au = 0.f, av = 0.f;
#pragma unroll
        for (int t = 0; t < 8; t++) {
            int c = lane + t * 32;
            au += qr[c] * g_wu[c];
            av += kr[c] * g_wv[c];
        }
#pragma unroll
        for (int o = 16; o > 0; o >>= 1) {
            au += __shfl_down_sync(0xffffffffu, au, o);
            av += __shfl_down_sync(0xffffffffu, av, o);
        }
        if (lane == 0) {
            g_u[row] = au;
            g_v[row] = av;
        }
    }
}

// ---------------------------------------------------------------------------
// main_fused (identical to R9 best): 128(i) x 64(j) tile, 8x4 micro,
// 256 threads, occ-3, padded smem, Rt epilogue, streaming stores.
// ---------------------------------------------------------------------------
__global__ __launch_bounds__(256, 3) void main_fused(const float* __restrict__ Key,
                                                     float* __restrict__ out) {
    int b = blockIdx.x;
    int tile = blockIdx.y;        // 0..127
    int it = tile >> 4;           // 0..7   (128 i-rows each)
    int jt = tile & 15;           // 0..15  (64 j-cols each)
    int tid = threadIdx.x;
    int tx = tid & 15;            // j dir (4 each)
    int ty = tid >> 4;            // i dir (8 each)
    int lrow = tid >> 2;          // 0..63
    int lk = (tid & 3) << 2;      // 0,4,8,12

    __shared__ __align__(16) float As[2][16][SA];  // [buf][k][i] padded
    __shared__ __align__(16) float Bs[2][16][SB];  // [buf][k][j] padded

    const float* Ap = g_A + ((size_t)b * N_SEQ + it * 128) * CDIM;
    const float* Bp = Key + ((size_t)b * N_SEQ + jt * 64) * CDIM;

    float4 ra0, ra1, rb0;

    auto ldg_stage = [&](int k0) {
        ra0 = *(const float4*)(Ap + (size_t)lrow * CDIM + k0 + lk);
        ra1 = *(const float4*)(Ap + (size_t)(64 + lrow) * CDIM + k0 + lk);
        rb0 = *(const float4*)(Bp + (size_t)lrow * CDIM + k0 + lk);
    };
    auto sts_stage = [&](int buf) {
        As[buf][lk + 0][lrow] = ra0.x; As[buf][lk + 1][lrow] = ra0.y;
        As[buf][lk + 2][lrow] = ra0.z; As[buf][lk + 3][lrow] = ra0.w;
        As[buf][lk + 0][64 + lrow] = ra1.x; As[buf][lk + 1][64 + lrow] = ra1.y;
        As[buf][lk + 2][64 + lrow] = ra1.z; As[buf][lk + 3][64 + lrow] = ra1.w;
        Bs[buf][lk + 0][lrow] = rb0.x; Bs[buf][lk + 1][lrow] = rb0.y;
        Bs[buf][lk + 2][lrow] = rb0.z; Bs[buf][lk + 3][lrow] = rb0.w;
    };

    float acc[8][4] = {};

    ldg_stage(0);
    sts_stage(0);
    __syncthreads();

    for (int s = 0; s < 16; s++) {
        int cur = s & 1;
        if (s < 15) ldg_stage((s + 1) * 16);
#pragma unroll
        for (int kk = 0; kk < 16; kk++) {
            float4 a0 = *(const float4*)&As[cur][kk][ty * 8];
            float4 a1 = *(const float4*)&As[cur][kk][ty * 8 + 4];
            float4 b0 = *(const float4*)&Bs[cur][kk][tx * 4];
            float av[8] = {a0.x, a0.y, a0.z, a0.w, a1.x, a1.y, a1.z, a1.w};
            float bv[4] = {b0.x, b0.y, b0.z, b0.w};
#pragma unroll
            for (int ii = 0; ii < 8; ii++)
#pragma unroll
                for (int jj = 0; jj < 4; jj++)
                    acc[ii][jj] += av[ii] * bv[jj];
        }
        if (s < 15) {
            sts_stage(cur ^ 1);    // ping-pong: single barrier per stage
            __syncthreads();
        }
    }

    // ---- epilogue: finalize scores ----
    int i0 = it * 128 + ty * 8;
    int j0 = jt * 64 + tx * 4;
    float cst = g_cst;
    float4 u0 = *(const float4*)&g_u[b * N_SEQ + i0];
    float4 u1 = *(const float4*)&g_u[b * N_SEQ + i0 + 4];
    float4 v0 = *(const float4*)&g_v[b * N_SEQ + j0];
    float uu[8] = {u0.x, u0.y, u0.z, u0.w, u1.x, u1.y, u1.z, u1.w};
    float vv[4] = {v0.x, v0.y, v0.z, v0.w};

#pragma unroll
    for (int ii = 0; ii < 8; ii++)
#pragma unroll
        for (int jj = 0; jj < 4; jj++)
            acc[ii][jj] = (acc[ii][jj] + uu[ii] + vv[jj] + cst) * 0.0625f;

    // ---- relation-mask multiply + streaming store (Rt: j-contiguous) ----
    const size_t NN = (size_t)N_SEQ * N_SEQ;
#pragma unroll
    for (int ii = 0; ii < 8; ii++) {
        int i = i0 + ii;
        const float* rtp = g_Rt + (size_t)i * N_SEQ + j0;
        float* op = out + (size_t)(b * RREL) * NN + (size_t)i * N_SEQ + j0;
#pragma unroll
        for (int r = 0; r < RREL; r++) {
            float4 m0 = __ldg((const float4*)(rtp + (size_t)r * NN));
            float4 o0;
            o0.x = acc[ii][0] * m0.x;
            o0.y = acc[ii][1] * m0.y;
            o0.z = acc[ii][2] * m0.z;
            o0.w = acc[ii][3] * m0.w;
            __stcs((float4*)(op + (size_t)r * NN), o0);
        }
    }
}

// ---------------------------------------------------------------------------
extern "C" void kernel_launch(void* const* d_in, const int* in_sizes, int n_in,
                              void* d_out, int out_size) {
    const float* Q    = (const float*)d_in[0];
    const float* K    = (const float*)d_in[1];
    const float* Wq   = (const float*)d_in[2];
    const float* bq   = (const float*)d_in[3];
    const float* Wk   = (const float*)d_in[4];
    const float* bk   = (const float*)d_in[5];
    const float* Rmap = (const float*)d_in[6];
    float* out = (float*)d_out;

    prep_w<<<257, 256>>>(Wq, Wk, bq, bk);
    mega<<<256 + 4096 + 1024, 256>>>(Q, K, Rmap);
    main_fused<<<dim3(8, 128), 256>>>(K, out);
}